// round 11
// baseline (speedup 1.0000x reference)
#include <cuda_runtime.h>
#include <cstdint>

#define BATCH 128
#define NPRI  8732
#define NOBJ  16
#define NCLS  21
#define THRESH 0.5f
#define K1B   18          // blocks per image in k1 (512 priors each; 18*512 >= 8732)
#define NCHUNK 9          // 1024-row chunks per image in k23
#define SMEM_DYN (1024 * NCLS * 4)   // 86016 B staging

// ---------------- scratch (static device globals; zero-initialized) ----------
__device__ float              g_btov[BATCH * NPRI];
__device__ uint8_t            g_bti [BATCH * NPRI];
__device__ unsigned long long g_best[BATCH * NOBJ];  // re-zeroed by k23 each launch
__device__ float              g_nposf[BATCH];
__device__ float              g_locs[BATCH];
__device__ float              g_pces[BATCH];
__device__ float              g_negs[BATCH];
__device__ unsigned int       g_ticket;              // reset by last block each launch

// ---------------- helpers -----------------------------------------------------
__device__ __forceinline__ float sl1(float x) {
    float a = fabsf(x);
    return (a < 1.f) ? 0.5f * a * a : a - 0.5f;
}

// two block-sums for the price of one barrier set; s must hold 64 floats
__device__ __forceinline__ float2 brSum2F(float a, float b, float* s) {
    int lane = threadIdx.x & 31, wid = threadIdx.x >> 5;
    int nw = (blockDim.x + 31) >> 5;
    #pragma unroll
    for (int o = 16; o; o >>= 1) {
        a += __shfl_xor_sync(0xFFFFFFFFu, a, o);
        b += __shfl_xor_sync(0xFFFFFFFFu, b, o);
    }
    if (lane == 0) { s[wid] = a; s[32 + wid] = b; }
    __syncthreads();
    if (wid == 0) {
        float ra = (lane < nw) ? s[lane] : 0.f;
        float rb = (lane < nw) ? s[32 + lane] : 0.f;
        #pragma unroll
        for (int o = 16; o; o >>= 1) {
            ra += __shfl_xor_sync(0xFFFFFFFFu, ra, o);
            rb += __shfl_xor_sync(0xFFFFFFFFu, rb, o);
        }
        if (lane == 0) { s[0] = ra; s[32] = rb; }
    }
    __syncthreads();
    float2 r = make_float2(s[0], s[32]);
    __syncthreads();
    return r;
}

// ---------------- K1: matching, 2 priors per thread ---------------------------
// grid = BATCH*K1B, 256 threads handle 512 priors (p and p+256).
__global__ __launch_bounds__(256)
void k1_match(const float* __restrict__ boxes, const float* __restrict__ priors) {
    const int b    = blockIdx.x / K1B;
    const int t    = blockIdx.x % K1B;
    const int tid  = threadIdx.x;
    const int lane = tid & 31, wid = tid >> 5;
    const int base = t * 512;
    const int p0   = base + tid;
    const int p1   = base + 256 + tid;
    const bool v0ok = (p0 < NPRI), v1ok = (p1 < NPRI);

    __shared__ float4 s_t[NOBJ];
    __shared__ float  s_ta[NOBJ];
    __shared__ unsigned long long s_red[NOBJ][8];

    if (tid < NOBJ) {
        float4 tb = ((const float4*)boxes)[b * NOBJ + tid];
        s_t[tid]  = tb;
        s_ta[tid] = (tb.z - tb.x) * (tb.w - tb.y);
    }
    __syncthreads();

    // invalid priors -> far degenerate box: v = 0, loses ties via group order
    float ax1 = 2.f, ay1 = 2.f, ax2 = 2.f, ay2 = 2.f, aa = 0.f;
    float bx1 = 2.f, by1 = 2.f, bx2 = 2.f, by2 = 2.f, ba = 0.f;
    if (v0ok) {
        float4 pr = ((const float4*)priors)[p0];
        float hw = 0.5f * pr.z, hh = 0.5f * pr.w;
        ax1 = pr.x - hw; ay1 = pr.y - hh; ax2 = pr.x + hw; ay2 = pr.y + hh;
        aa = pr.z * pr.w;
    }
    if (v1ok) {
        float4 pr = ((const float4*)priors)[p1];
        float hw = 0.5f * pr.z, hh = 0.5f * pr.w;
        bx1 = pr.x - hw; by1 = pr.y - hh; bx2 = pr.x + hw; by2 = pr.y + hh;
        ba = pr.z * pr.w;
    }

    float pv0 = -1.f, pv1 = -1.f; int po0 = 0, po1 = 0;
    #pragma unroll
    for (int o = 0; o < NOBJ; o++) {
        float4 tb = s_t[o]; float ta = s_ta[o];
        float ix0 = fmaxf(fminf(tb.z, ax2) - fmaxf(tb.x, ax1), 0.f);
        float iy0 = fmaxf(fminf(tb.w, ay2) - fmaxf(tb.y, ay1), 0.f);
        float in0 = ix0 * iy0;
        float v0  = __fdividef(in0, (ta + aa) - in0);
        float ix1 = fmaxf(fminf(tb.z, bx2) - fmaxf(tb.x, bx1), 0.f);
        float iy1 = fmaxf(fminf(tb.w, by2) - fmaxf(tb.y, by1), 0.f);
        float in1 = ix1 * iy1;
        float v1  = __fdividef(in1, (ta + ba) - in1);
        bool g0 = v0 > pv0; pv0 = g0 ? v0 : pv0; po0 = g0 ? o : po0;
        bool g1 = v1 > pv1; pv1 = g1 ? v1 : pv1; po1 = g1 ? o : po1;
        // per-truth warp max; ties -> smallest p (p0-group before p1-group)
        unsigned vb0 = __float_as_uint(v0), vb1 = __float_as_uint(v1);
        unsigned vm  = __reduce_max_sync(0xFFFFFFFFu, vb0 > vb1 ? vb0 : vb1);
        unsigned m0  = __ballot_sync(0xFFFFFFFFu, vb0 == vm);
        unsigned m1  = __ballot_sync(0xFFFFFFFFu, vb1 == vm);
        bool win = m0 ? (lane == __ffs(m0) - 1) : (lane == __ffs(m1) - 1);
        if (win) {
            unsigned wp = m0 ? (unsigned)p0 : (unsigned)p1;
            s_red[o][wid] = ((unsigned long long)vm << 32)
                          | (0xFFFFFFFFu - wp);
        }
    }

    // store per-prior result; exact div.rn only when near the 0.5 threshold
    if (v0ok) {
        float ov = pv0;
        if (fabsf(pv0 - 0.5f) < 1e-3f) {
            float4 tb = s_t[po0];
            float ix = fmaxf(fminf(tb.z, ax2) - fmaxf(tb.x, ax1), 0.f);
            float iy = fmaxf(fminf(tb.w, ay2) - fmaxf(tb.y, ay1), 0.f);
            float in = ix * iy;
            ov = in / ((s_ta[po0] + aa) - in);
        }
        g_btov[b * NPRI + p0] = ov;
        g_bti [b * NPRI + p0] = (uint8_t)po0;
    }
    if (v1ok) {
        float ov = pv1;
        if (fabsf(pv1 - 0.5f) < 1e-3f) {
            float4 tb = s_t[po1];
            float ix = fmaxf(fminf(tb.z, bx2) - fmaxf(tb.x, bx1), 0.f);
            float iy = fmaxf(fminf(tb.w, by2) - fmaxf(tb.y, by1), 0.f);
            float in = ix * iy;
            ov = in / ((s_ta[po1] + ba) - in);
        }
        g_btov[b * NPRI + p1] = ov;
        g_bti [b * NPRI + p1] = (uint8_t)po1;
    }

    __syncthreads();
    if (tid < NOBJ) {
        unsigned long long m = 0ULL;
        #pragma unroll
        for (int w = 0; w < 8; w++) {
            unsigned long long u = s_red[tid][w];
            m = (u > m) ? u : m;
        }
        atomicMax(&g_best[b * NOBJ + tid], m);   // order-independent merge
    }
}

// ---------------- K23: fused ce + loc loss + top-K + final --------------------
// one 1024-thread block per image; conf staged in 9 chunks of 1024 rows in
// 86KB dynamic shared (coalesced float4), ce/ct computed inline.
__global__ __launch_bounds__(1024)
void k23_fused(const float* __restrict__ conf,
               const int*   __restrict__ labels,
               const float* __restrict__ loc_preds,
               const float* __restrict__ boxes,
               const float* __restrict__ priors,
               float* __restrict__ out) {
    extern __shared__ float s_rows[];   // 1024 * NCLS floats
    const int b    = blockIdx.x;
    const int tid  = threadIdx.x;
    const int lane = tid & 31, wid = tid >> 5;

    __shared__ float    s_tx1[NOBJ], s_ty1[NOBJ], s_tx2[NOBJ], s_ty2[NOBJ];
    __shared__ int      s_lab[NOBJ];
    __shared__ unsigned s_fp[NOBJ];
    __shared__ float    s_redf[64];
    __shared__ int      s_cnt[2][3][32];
    __shared__ int      s_bc[4];

    if (tid < NOBJ) {
        s_tx1[tid] = boxes[(b * NOBJ + tid) * 4 + 0];
        s_ty1[tid] = boxes[(b * NOBJ + tid) * 4 + 1];
        s_tx2[tid] = boxes[(b * NOBJ + tid) * 4 + 2];
        s_ty2[tid] = boxes[(b * NOBJ + tid) * 4 + 3];
        s_lab[tid] = labels[b * NOBJ + tid];
        s_fp[tid]  = 0xFFFFFFFFu - (unsigned)(g_best[b * NOBJ + tid] & 0xFFFFFFFFULL);
        g_best[b * NOBJ + tid] = 0ULL;   // re-zero for next graph replay
    }
    __syncthreads();

    unsigned u[NCHUNK];
    float posce = 0.f, locsum = 0.f;
    int isp = 0;

    for (int i = 0; i < NCHUNK; i++) {
        const int r0 = i * 1024;
        const int nr = min(1024, NPRI - r0);
        const int nf4 = nr * NCLS / 4;            // nr*21 divisible by 4 here
        const float4* src = (const float4*)(conf + ((size_t)b * NPRI + r0) * NCLS);
        for (int j = tid; j < nf4; j += 1024)
            ((float4*)s_rows)[j] = src[j];
        __syncthreads();

        u[i] = 0u;
        if (tid < nr) {
            const int p = r0 + tid;
            const size_t idx = (size_t)b * NPRI + p;
            float ov = g_btov[idx];
            int   o  = g_bti[idx];
            #pragma unroll
            for (int oo = 0; oo < NOBJ; oo++) {   // ascending: last truth wins
                bool f = (s_fp[oo] == (unsigned)p);
                ov = f ? 2.0f : ov;
                o  = f ? oo : o;
            }
            const int ct = (ov < THRESH) ? 0 : (s_lab[o] + 1);
            const float* v = s_rows + tid * NCLS; // stride 21: conflict-free
            float m = v[0];
            #pragma unroll
            for (int c = 1; c < NCLS; c++) m = fmaxf(m, v[c]);
            float ssum = 0.f;
            #pragma unroll
            for (int c = 0; c < NCLS; c++) ssum += __expf(v[c] - m);
            float ce = m + __logf(ssum) - v[ct];
            if (ct > 0) {
                posce += ce; isp++;
                float tx1 = s_tx1[o], ty1 = s_ty1[o], tx2 = s_tx2[o], ty2 = s_ty2[o];
                float4 pr = ((const float4*)priors)[p];
                float g0 = ((tx1 + tx2) * 0.5f - pr.x) / (0.1f * pr.z);
                float g1 = ((ty1 + ty2) * 0.5f - pr.y) / (0.1f * pr.w);
                float g2 = __logf((tx2 - tx1) / pr.z) * 5.0f;
                float g3 = __logf((ty2 - ty1) / pr.w) * 5.0f;
                float4 lp = ((const float4*)loc_preds)[(size_t)b * NPRI + p];
                locsum += sl1(lp.x - g0) + sl1(lp.y - g1)
                        + sl1(lp.z - g2) + sl1(lp.w - g3);
            } else {
                u[i] = __float_as_uint(ce);       // negatives only; ce >= 0
            }
        }
        __syncthreads();                          // buffer reused next chunk
    }

    // npos: block reduce (exact int)
    int nw = __reduce_add_sync(0xFFFFFFFFu, isp);
    if (lane == 0) s_cnt[0][0][wid] = nw;
    __syncthreads();
    const int npos = __reduce_add_sync(0xFFFFFFFFu, s_cnt[0][0][lane]);
    __syncthreads();

    float2 pl = brSum2F(posce, locsum, s_redf);
    const float pcT = pl.x, lcT = pl.y;

    int K = 3 * npos; if (K > NPRI) K = NPRI;
    float negsum = 0.f;
    if (K > 0) {
        unsigned prefix = 0u;
        int par = 0;
        for (int sh = 29; sh >= 1; sh -= 2) {     // 2 bits/round, 1 barrier
            unsigned cA = prefix | (1u << sh);
            unsigned cB = prefix | (2u << sh);
            unsigned cC = prefix | (3u << sh);
            int n1 = 0, n2 = 0, n3 = 0;
            #pragma unroll
            for (int i = 0; i < NCHUNK; i++) {
                n1 += (u[i] >= cA);
                n2 += (u[i] >= cB);
                n3 += (u[i] >= cC);
            }
            n1 = __reduce_add_sync(0xFFFFFFFFu, n1);
            n2 = __reduce_add_sync(0xFFFFFFFFu, n2);
            n3 = __reduce_add_sync(0xFFFFFFFFu, n3);
            if (lane == 0) {
                s_cnt[par][0][wid] = n1;
                s_cnt[par][1][wid] = n2;
                s_cnt[par][2][wid] = n3;
            }
            __syncthreads();
            int t1 = __reduce_add_sync(0xFFFFFFFFu, s_cnt[par][0][lane]);
            int t2 = __reduce_add_sync(0xFFFFFFFFu, s_cnt[par][1][lane]);
            int t3 = __reduce_add_sync(0xFFFFFFFFu, s_cnt[par][2][lane]);
            prefix |= (t3 >= K) ? (3u << sh)
                    : (t2 >= K) ? (2u << sh)
                    : (t1 >= K) ? (1u << sh) : 0u;
            par ^= 1;
        }
        {   // final bit 0
            unsigned cand = prefix | 1u;
            int n = 0;
            #pragma unroll
            for (int i = 0; i < NCHUNK; i++) n += (u[i] >= cand);
            n = __reduce_add_sync(0xFFFFFFFFu, n);
            if (lane == 0) s_cnt[par][0][wid] = n;
            __syncthreads();
            int tot = __reduce_add_sync(0xFFFFFFFFu, s_cnt[par][0][lane]);
            if (tot >= K) prefix |= 1u;
        }
        float vK = __uint_as_float(prefix);       // exact K-th largest
        float sgt = 0.f; int cgt = 0;
        #pragma unroll
        for (int i = 0; i < NCHUNK; i++) {
            float v = __uint_as_float(u[i]);
            if (v > vK) { sgt += v; cgt++; }
        }
        float2 sc = brSum2F(sgt, (float)cgt, s_redf);   // cgt < 2^24: exact
        negsum = sc.x + ((float)K - sc.y) * vK;         // ties handled exactly
    }

    if (tid == 0) {
        g_locs[b]  = lcT;
        g_pces[b]  = pcT;
        g_negs[b]  = negsum;
        g_nposf[b] = (float)npos;
    }
    __threadfence();
    __syncthreads();
    if (tid == 0) {
        unsigned old = atomicAdd(&g_ticket, 1u);
        s_bc[2] = (old == BATCH - 1) ? 1 : 0;
    }
    __syncthreads();

    if (s_bc[2]) {   // last block: final reduction over images
        float np = 0.f, lc = 0.f, pc = 0.f, ns = 0.f;
        if (tid < BATCH) {
            np = __ldcg(&g_nposf[tid]);
            lc = __ldcg(&g_locs[tid]);
            pc = __ldcg(&g_pces[tid]);
            ns = __ldcg(&g_negs[tid]);
        }
        float2 r1 = brSum2F(np, lc, s_redf);
        float2 r2 = brSum2F(pc, ns, s_redf);
        if (tid == 0) {
            out[0] = (r2.x + r2.y) / (r1.x + 1e-7f) + r1.y / (4.0f * r1.x);
            g_ticket = 0u;
        }
    }
}

// ---------------- launch ------------------------------------------------------
extern "C" void kernel_launch(void* const* d_in, const int* in_sizes, int n_in,
                              void* d_out, int out_size) {
    const float* loc_preds  = (const float*)d_in[0];
    const float* conf_preds = (const float*)d_in[1];
    const float* boxes      = (const float*)d_in[2];
    const int*   labels     = (const int*)d_in[3];
    const float* priors     = (const float*)d_in[4];
    float* out = (float*)d_out;

    cudaFuncSetAttribute(k23_fused,
                         cudaFuncAttributeMaxDynamicSharedMemorySize, SMEM_DYN);

    k1_match<<<BATCH * K1B, 256>>>(boxes, priors);
    k23_fused<<<BATCH, 1024, SMEM_DYN>>>(conf_preds, labels, loc_preds,
                                         boxes, priors, out);
    (void)in_sizes; (void)n_in; (void)out_size;
}

// round 13
// speedup vs baseline: 1.0231x; 1.0231x over previous
#include <cuda_runtime.h>
#include <cstdint>

#define BATCH 128
#define NPRI  8732
#define NOBJ  16
#define NCLS  21
#define THRESH 0.5f
#define K1B   18          // blocks per image in k1 (512 priors each; 18*512 >= 8732)
#define NCHUNK 9          // 1024-row chunks per image in k23
#define CHUNK_F4 (1024 * NCLS / 4)          // 5376 float4 per full chunk
#define BUF_FLOATS (1024 * NCLS)            // floats per buffer
#define SMEM_DYN (2 * BUF_FLOATS * 4)       // 172032 B double buffer

// ---------------- scratch (static device globals; zero-initialized) ----------
__device__ float              g_btov[BATCH * NPRI];
__device__ uint8_t            g_bti [BATCH * NPRI];
__device__ unsigned long long g_best[BATCH * NOBJ];  // re-zeroed by k23 each launch
__device__ float              g_nposf[BATCH];
__device__ float              g_locs[BATCH];
__device__ float              g_pces[BATCH];
__device__ float              g_negs[BATCH];
__device__ unsigned int       g_ticket;              // reset by last block each launch

// ---------------- helpers -----------------------------------------------------
__device__ __forceinline__ float sl1(float x) {
    float a = fabsf(x);
    return (a < 1.f) ? 0.5f * a * a : a - 0.5f;
}

__device__ __forceinline__ void cp16(uint32_t dst_smem, const void* src) {
    asm volatile("cp.async.cg.shared.global [%0], [%1], 16;\n"
                 :: "r"(dst_smem), "l"(src));
}
#define CP_COMMIT() asm volatile("cp.async.commit_group;\n" ::: "memory")
#define CP_WAIT(n)  asm volatile("cp.async.wait_group %0;\n" :: "n"(n) : "memory")

// two block-sums for the price of one barrier set; s must hold 64 floats
__device__ __forceinline__ float2 brSum2F(float a, float b, float* s) {
    int lane = threadIdx.x & 31, wid = threadIdx.x >> 5;
    int nw = (blockDim.x + 31) >> 5;
    #pragma unroll
    for (int o = 16; o; o >>= 1) {
        a += __shfl_xor_sync(0xFFFFFFFFu, a, o);
        b += __shfl_xor_sync(0xFFFFFFFFu, b, o);
    }
    if (lane == 0) { s[wid] = a; s[32 + wid] = b; }
    __syncthreads();
    if (wid == 0) {
        float ra = (lane < nw) ? s[lane] : 0.f;
        float rb = (lane < nw) ? s[32 + lane] : 0.f;
        #pragma unroll
        for (int o = 16; o; o >>= 1) {
            ra += __shfl_xor_sync(0xFFFFFFFFu, ra, o);
            rb += __shfl_xor_sync(0xFFFFFFFFu, rb, o);
        }
        if (lane == 0) { s[0] = ra; s[32] = rb; }
    }
    __syncthreads();
    float2 r = make_float2(s[0], s[32]);
    __syncthreads();
    return r;
}

// ---------------- K1: matching, 2 priors per thread ---------------------------
__global__ __launch_bounds__(256)
void k1_match(const float* __restrict__ boxes, const float* __restrict__ priors) {
    const int b    = blockIdx.x / K1B;
    const int t    = blockIdx.x % K1B;
    const int tid  = threadIdx.x;
    const int lane = tid & 31, wid = tid >> 5;
    const int base = t * 512;
    const int p0   = base + tid;
    const int p1   = base + 256 + tid;
    const bool v0ok = (p0 < NPRI), v1ok = (p1 < NPRI);

    __shared__ float4 s_t[NOBJ];
    __shared__ float  s_ta[NOBJ];
    __shared__ unsigned long long s_red[NOBJ][8];

    if (tid < NOBJ) {
        float4 tb = ((const float4*)boxes)[b * NOBJ + tid];
        s_t[tid]  = tb;
        s_ta[tid] = (tb.z - tb.x) * (tb.w - tb.y);
    }
    __syncthreads();

    float ax1 = 2.f, ay1 = 2.f, ax2 = 2.f, ay2 = 2.f, aa = 0.f;
    float bx1 = 2.f, by1 = 2.f, bx2 = 2.f, by2 = 2.f, ba = 0.f;
    if (v0ok) {
        float4 pr = ((const float4*)priors)[p0];
        float hw = 0.5f * pr.z, hh = 0.5f * pr.w;
        ax1 = pr.x - hw; ay1 = pr.y - hh; ax2 = pr.x + hw; ay2 = pr.y + hh;
        aa = pr.z * pr.w;
    }
    if (v1ok) {
        float4 pr = ((const float4*)priors)[p1];
        float hw = 0.5f * pr.z, hh = 0.5f * pr.w;
        bx1 = pr.x - hw; by1 = pr.y - hh; bx2 = pr.x + hw; by2 = pr.y + hh;
        ba = pr.z * pr.w;
    }

    float pv0 = -1.f, pv1 = -1.f; int po0 = 0, po1 = 0;
    #pragma unroll
    for (int o = 0; o < NOBJ; o++) {
        float4 tb = s_t[o]; float ta = s_ta[o];
        float ix0 = fmaxf(fminf(tb.z, ax2) - fmaxf(tb.x, ax1), 0.f);
        float iy0 = fmaxf(fminf(tb.w, ay2) - fmaxf(tb.y, ay1), 0.f);
        float in0 = ix0 * iy0;
        float v0  = __fdividef(in0, (ta + aa) - in0);
        float ix1 = fmaxf(fminf(tb.z, bx2) - fmaxf(tb.x, bx1), 0.f);
        float iy1 = fmaxf(fminf(tb.w, by2) - fmaxf(tb.y, by1), 0.f);
        float in1 = ix1 * iy1;
        float v1  = __fdividef(in1, (ta + ba) - in1);
        bool g0 = v0 > pv0; pv0 = g0 ? v0 : pv0; po0 = g0 ? o : po0;
        bool g1 = v1 > pv1; pv1 = g1 ? v1 : pv1; po1 = g1 ? o : po1;
        unsigned vb0 = __float_as_uint(v0), vb1 = __float_as_uint(v1);
        unsigned vm  = __reduce_max_sync(0xFFFFFFFFu, vb0 > vb1 ? vb0 : vb1);
        unsigned m0  = __ballot_sync(0xFFFFFFFFu, vb0 == vm);
        unsigned m1  = __ballot_sync(0xFFFFFFFFu, vb1 == vm);
        bool win = m0 ? (lane == __ffs(m0) - 1) : (lane == __ffs(m1) - 1);
        if (win) {
            unsigned wp = m0 ? (unsigned)p0 : (unsigned)p1;
            s_red[o][wid] = ((unsigned long long)vm << 32)
                          | (0xFFFFFFFFu - wp);
        }
    }

    if (v0ok) {
        float ov = pv0;
        if (fabsf(pv0 - 0.5f) < 1e-3f) {
            float4 tb = s_t[po0];
            float ix = fmaxf(fminf(tb.z, ax2) - fmaxf(tb.x, ax1), 0.f);
            float iy = fmaxf(fminf(tb.w, ay2) - fmaxf(tb.y, ay1), 0.f);
            float in = ix * iy;
            ov = in / ((s_ta[po0] + aa) - in);
        }
        g_btov[b * NPRI + p0] = ov;
        g_bti [b * NPRI + p0] = (uint8_t)po0;
    }
    if (v1ok) {
        float ov = pv1;
        if (fabsf(pv1 - 0.5f) < 1e-3f) {
            float4 tb = s_t[po1];
            float ix = fmaxf(fminf(tb.z, bx2) - fmaxf(tb.x, bx1), 0.f);
            float iy = fmaxf(fminf(tb.w, by2) - fmaxf(tb.y, by1), 0.f);
            float in = ix * iy;
            ov = in / ((s_ta[po1] + ba) - in);
        }
        g_btov[b * NPRI + p1] = ov;
        g_bti [b * NPRI + p1] = (uint8_t)po1;
    }

    __syncthreads();
    if (tid < NOBJ) {
        unsigned long long m = 0ULL;
        #pragma unroll
        for (int w = 0; w < 8; w++) {
            unsigned long long u = s_red[tid][w];
            m = (u > m) ? u : m;
        }
        atomicMax(&g_best[b * NOBJ + tid], m);
    }
}

// ---------------- K23: fused ce + loc + top-K, cp.async double-buffered -------
__global__ __launch_bounds__(1024)
void k23_fused(const float* __restrict__ conf,
               const int*   __restrict__ labels,
               const float* __restrict__ loc_preds,
               const float* __restrict__ boxes,
               const float* __restrict__ priors,
               float* __restrict__ out) {
    extern __shared__ float s_rows[];   // 2 buffers x 1024*NCLS floats
    const int b    = blockIdx.x;
    const int tid  = threadIdx.x;
    const int lane = tid & 31, wid = tid >> 5;

    __shared__ float    s_tx1[NOBJ], s_ty1[NOBJ], s_tx2[NOBJ], s_ty2[NOBJ];
    __shared__ int      s_lab[NOBJ];
    __shared__ unsigned s_fp[NOBJ];
    __shared__ float    s_redf[64];
    __shared__ int      s_cnt[2][3][32];
    __shared__ int      s_bc[4];

    if (tid < NOBJ) {
        s_tx1[tid] = boxes[(b * NOBJ + tid) * 4 + 0];
        s_ty1[tid] = boxes[(b * NOBJ + tid) * 4 + 1];
        s_tx2[tid] = boxes[(b * NOBJ + tid) * 4 + 2];
        s_ty2[tid] = boxes[(b * NOBJ + tid) * 4 + 3];
        s_lab[tid] = labels[b * NOBJ + tid];
        s_fp[tid]  = 0xFFFFFFFFu - (unsigned)(g_best[b * NOBJ + tid] & 0xFFFFFFFFULL);
        g_best[b * NOBJ + tid] = 0ULL;   // re-zero for next graph replay
    }
    __syncthreads();

    const uint32_t smem_base = (uint32_t)__cvta_generic_to_shared(s_rows);
    const float*   conf_img  = conf + (size_t)b * NPRI * NCLS;

    // prefetch chunk 0
    {
        const int nf4 = CHUNK_F4;
        const float4* src = (const float4*)conf_img;
        for (int j = tid; j < nf4; j += 1024)
            cp16(smem_base + j * 16, src + j);
        CP_COMMIT();
    }

    unsigned u[NCHUNK];
    float posce = 0.f, locsum = 0.f;
    int isp = 0;

    for (int i = 0; i < NCHUNK; i++) {
        // prefetch chunk i+1 into the other buffer
        if (i + 1 < NCHUNK) {
            const int r0n = (i + 1) * 1024;
            const int nrn = min(1024, NPRI - r0n);
            const int nf4 = nrn * NCLS / 4;
            const uint32_t dstb = smem_base + ((i + 1) & 1) * (BUF_FLOATS * 4);
            const float4* src = (const float4*)(conf_img + (size_t)r0n * NCLS);
            for (int j = tid; j < nf4; j += 1024)
                cp16(dstb + j * 16, src + j);
            CP_COMMIT();
            CP_WAIT(1);   // chunk i complete; i+1 still in flight
        } else {
            CP_WAIT(0);
        }
        __syncthreads();

        const int r0 = i * 1024;
        const int nr = min(1024, NPRI - r0);
        const float* buf = s_rows + (i & 1) * BUF_FLOATS;

        u[i] = 0u;
        if (tid < nr) {
            const int p = r0 + tid;
            const size_t idx = (size_t)b * NPRI + p;
            float ov = g_btov[idx];
            int   o  = g_bti[idx];
            #pragma unroll
            for (int oo = 0; oo < NOBJ; oo++) {   // ascending: last truth wins
                bool f = (s_fp[oo] == (unsigned)p);
                ov = f ? 2.0f : ov;
                o  = f ? oo : o;
            }
            const int ct = (ov < THRESH) ? 0 : (s_lab[o] + 1);
            const float* v = buf + tid * NCLS;    // stride 21: conflict-free
            float m = v[0];
            #pragma unroll
            for (int c = 1; c < NCLS; c++) m = fmaxf(m, v[c]);
            float ssum = 0.f;
            #pragma unroll
            for (int c = 0; c < NCLS; c++) ssum += __expf(v[c] - m);
            float ce = m + __logf(ssum) - v[ct];
            if (ct > 0) {
                posce += ce; isp++;
                float tx1 = s_tx1[o], ty1 = s_ty1[o], tx2 = s_tx2[o], ty2 = s_ty2[o];
                float4 pr = ((const float4*)priors)[p];
                float g0 = ((tx1 + tx2) * 0.5f - pr.x) / (0.1f * pr.z);
                float g1 = ((ty1 + ty2) * 0.5f - pr.y) / (0.1f * pr.w);
                float g2 = __logf((tx2 - tx1) / pr.z) * 5.0f;
                float g3 = __logf((ty2 - ty1) / pr.w) * 5.0f;
                float4 lp = ((const float4*)loc_preds)[(size_t)b * NPRI + p];
                locsum += sl1(lp.x - g0) + sl1(lp.y - g1)
                        + sl1(lp.z - g2) + sl1(lp.w - g3);
            } else {
                u[i] = __float_as_uint(ce);       // negatives only; ce >= 0
            }
        }
        __syncthreads();   // buffer (i&1) safe to overwrite at iter i+2
    }

    // npos: block reduce (exact int)
    int nw = __reduce_add_sync(0xFFFFFFFFu, isp);
    if (lane == 0) s_cnt[0][0][wid] = nw;
    __syncthreads();
    const int npos = __reduce_add_sync(0xFFFFFFFFu, s_cnt[0][0][lane]);
    __syncthreads();

    float2 pl = brSum2F(posce, locsum, s_redf);
    const float pcT = pl.x, lcT = pl.y;

    int K = 3 * npos; if (K > NPRI) K = NPRI;
    float negsum = 0.f;
    if (K > 0) {
        unsigned prefix = 0u;
        int par = 0;
        for (int sh = 29; sh >= 1; sh -= 2) {     // 2 bits/round, 1 barrier
            unsigned cA = prefix | (1u << sh);
            unsigned cB = prefix | (2u << sh);
            unsigned cC = prefix | (3u << sh);
            int n1 = 0, n2 = 0, n3 = 0;
            #pragma unroll
            for (int i = 0; i < NCHUNK; i++) {
                n1 += (u[i] >= cA);
                n2 += (u[i] >= cB);
                n3 += (u[i] >= cC);
            }
            n1 = __reduce_add_sync(0xFFFFFFFFu, n1);
            n2 = __reduce_add_sync(0xFFFFFFFFu, n2);
            n3 = __reduce_add_sync(0xFFFFFFFFu, n3);
            if (lane == 0) {
                s_cnt[par][0][wid] = n1;
                s_cnt[par][1][wid] = n2;
                s_cnt[par][2][wid] = n3;
            }
            __syncthreads();
            int t1 = __reduce_add_sync(0xFFFFFFFFu, s_cnt[par][0][lane]);
            int t2 = __reduce_add_sync(0xFFFFFFFFu, s_cnt[par][1][lane]);
            int t3 = __reduce_add_sync(0xFFFFFFFFu, s_cnt[par][2][lane]);
            prefix |= (t3 >= K) ? (3u << sh)
                    : (t2 >= K) ? (2u << sh)
                    : (t1 >= K) ? (1u << sh) : 0u;
            par ^= 1;
        }
        {   // final bit 0
            unsigned cand = prefix | 1u;
            int n = 0;
            #pragma unroll
            for (int i = 0; i < NCHUNK; i++) n += (u[i] >= cand);
            n = __reduce_add_sync(0xFFFFFFFFu, n);
            if (lane == 0) s_cnt[par][0][wid] = n;
            __syncthreads();
            int tot = __reduce_add_sync(0xFFFFFFFFu, s_cnt[par][0][lane]);
            if (tot >= K) prefix |= 1u;
        }
        float vK = __uint_as_float(prefix);       // exact K-th largest
        float sgt = 0.f; int cgt = 0;
        #pragma unroll
        for (int i = 0; i < NCHUNK; i++) {
            float v = __uint_as_float(u[i]);
            if (v > vK) { sgt += v; cgt++; }
        }
        float2 sc = brSum2F(sgt, (float)cgt, s_redf);   // cgt < 2^24: exact
        negsum = sc.x + ((float)K - sc.y) * vK;         // ties handled exactly
    }

    if (tid == 0) {
        g_locs[b]  = lcT;
        g_pces[b]  = pcT;
        g_negs[b]  = negsum;
        g_nposf[b] = (float)npos;
    }
    __threadfence();
    __syncthreads();
    if (tid == 0) {
        unsigned old = atomicAdd(&g_ticket, 1u);
        s_bc[2] = (old == BATCH - 1) ? 1 : 0;
    }
    __syncthreads();

    if (s_bc[2]) {   // last block: final reduction over images
        float np = 0.f, lc = 0.f, pc = 0.f, ns = 0.f;
        if (tid < BATCH) {
            np = __ldcg(&g_nposf[tid]);
            lc = __ldcg(&g_locs[tid]);
            pc = __ldcg(&g_pces[tid]);
            ns = __ldcg(&g_negs[tid]);
        }
        float2 r1 = brSum2F(np, lc, s_redf);
        float2 r2 = brSum2F(pc, ns, s_redf);
        if (tid == 0) {
            out[0] = (r2.x + r2.y) / (r1.x + 1e-7f) + r1.y / (4.0f * r1.x);
            g_ticket = 0u;
        }
    }
}

// ---------------- launch ------------------------------------------------------
extern "C" void kernel_launch(void* const* d_in, const int* in_sizes, int n_in,
                              void* d_out, int out_size) {
    const float* loc_preds  = (const float*)d_in[0];
    const float* conf_preds = (const float*)d_in[1];
    const float* boxes      = (const float*)d_in[2];
    const int*   labels     = (const int*)d_in[3];
    const float* priors     = (const float*)d_in[4];
    float* out = (float*)d_out;

    cudaFuncSetAttribute(k23_fused,
                         cudaFuncAttributeMaxDynamicSharedMemorySize, SMEM_DYN);

    k1_match<<<BATCH * K1B, 256>>>(boxes, priors);
    k23_fused<<<BATCH, 1024, SMEM_DYN>>>(conf_preds, labels, loc_preds,
                                         boxes, priors, out);
    (void)in_sizes; (void)n_in; (void)out_size;
}

// round 14
// speedup vs baseline: 1.0841x; 1.0597x over previous
#include <cuda_runtime.h>
#include <cstdint>

#define BATCH 128
#define NPRI  8732
#define NOBJ  16
#define NCLS  21
#define THRESH 0.5f
#define K1B   18        // k1 blocks per image (512 priors each)
#define CEB   35        // k2 blocks per image (256 priors each)

// ---------------- scratch (static device globals; zero-initialized) ----------
__device__ float              g_btov[BATCH * NPRI];
__device__ uint8_t            g_bti [BATCH * NPRI];
__device__ uint8_t            g_ct  [BATCH * NPRI];
__device__ uint8_t            g_of  [BATCH * NPRI];
__device__ float              g_ce  [BATCH * NPRI];
__device__ unsigned long long g_best[BATCH * NOBJ];  // re-zeroed by k3 each launch
__device__ int                g_npos[BATCH];         // re-zeroed by k3 each launch
__device__ float              g_nposf[BATCH];
__device__ float              g_locs[BATCH];
__device__ float              g_pces[BATCH];
__device__ float              g_negs[BATCH];
__device__ unsigned int       g_ticket;              // reset by last block each launch

// ---------------- helpers -----------------------------------------------------
__device__ __forceinline__ float sl1(float x) {
    float a = fabsf(x);
    return (a < 1.f) ? 0.5f * a * a : a - 0.5f;
}

// two block-sums for one barrier set; s must hold 64 floats
__device__ __forceinline__ float2 brSum2F(float a, float b, float* s) {
    int lane = threadIdx.x & 31, wid = threadIdx.x >> 5;
    int nw = (blockDim.x + 31) >> 5;
    #pragma unroll
    for (int o = 16; o; o >>= 1) {
        a += __shfl_xor_sync(0xFFFFFFFFu, a, o);
        b += __shfl_xor_sync(0xFFFFFFFFu, b, o);
    }
    if (lane == 0) { s[wid] = a; s[32 + wid] = b; }
    __syncthreads();
    if (wid == 0) {
        float ra = (lane < nw) ? s[lane] : 0.f;
        float rb = (lane < nw) ? s[32 + lane] : 0.f;
        #pragma unroll
        for (int o = 16; o; o >>= 1) {
            ra += __shfl_xor_sync(0xFFFFFFFFu, ra, o);
            rb += __shfl_xor_sync(0xFFFFFFFFu, rb, o);
        }
        if (lane == 0) { s[0] = ra; s[32] = rb; }
    }
    __syncthreads();
    float2 r = make_float2(s[0], s[32]);
    __syncthreads();
    return r;
}

// ---------------- K1: matching, 2 priors per thread (R13, best measured) ------
__global__ __launch_bounds__(256)
void k1_match(const float* __restrict__ boxes, const float* __restrict__ priors) {
    const int b    = blockIdx.x / K1B;
    const int t    = blockIdx.x % K1B;
    const int tid  = threadIdx.x;
    const int lane = tid & 31, wid = tid >> 5;
    const int base = t * 512;
    const int p0   = base + tid;
    const int p1   = base + 256 + tid;
    const bool v0ok = (p0 < NPRI), v1ok = (p1 < NPRI);

    __shared__ float4 s_t[NOBJ];
    __shared__ float  s_ta[NOBJ];
    __shared__ unsigned long long s_red[NOBJ][8];

    if (tid < NOBJ) {
        float4 tb = ((const float4*)boxes)[b * NOBJ + tid];
        s_t[tid]  = tb;
        s_ta[tid] = (tb.z - tb.x) * (tb.w - tb.y);
    }
    __syncthreads();

    float ax1 = 2.f, ay1 = 2.f, ax2 = 2.f, ay2 = 2.f, aa = 0.f;
    float bx1 = 2.f, by1 = 2.f, bx2 = 2.f, by2 = 2.f, ba = 0.f;
    if (v0ok) {
        float4 pr = ((const float4*)priors)[p0];
        float hw = 0.5f * pr.z, hh = 0.5f * pr.w;
        ax1 = pr.x - hw; ay1 = pr.y - hh; ax2 = pr.x + hw; ay2 = pr.y + hh;
        aa = pr.z * pr.w;
    }
    if (v1ok) {
        float4 pr = ((const float4*)priors)[p1];
        float hw = 0.5f * pr.z, hh = 0.5f * pr.w;
        bx1 = pr.x - hw; by1 = pr.y - hh; bx2 = pr.x + hw; by2 = pr.y + hh;
        ba = pr.z * pr.w;
    }

    float pv0 = -1.f, pv1 = -1.f; int po0 = 0, po1 = 0;
    #pragma unroll
    for (int o = 0; o < NOBJ; o++) {
        float4 tb = s_t[o]; float ta = s_ta[o];
        float ix0 = fmaxf(fminf(tb.z, ax2) - fmaxf(tb.x, ax1), 0.f);
        float iy0 = fmaxf(fminf(tb.w, ay2) - fmaxf(tb.y, ay1), 0.f);
        float in0 = ix0 * iy0;
        float v0  = __fdividef(in0, (ta + aa) - in0);
        float ix1 = fmaxf(fminf(tb.z, bx2) - fmaxf(tb.x, bx1), 0.f);
        float iy1 = fmaxf(fminf(tb.w, by2) - fmaxf(tb.y, by1), 0.f);
        float in1 = ix1 * iy1;
        float v1  = __fdividef(in1, (ta + ba) - in1);
        bool g0 = v0 > pv0; pv0 = g0 ? v0 : pv0; po0 = g0 ? o : po0;
        bool g1 = v1 > pv1; pv1 = g1 ? v1 : pv1; po1 = g1 ? o : po1;
        unsigned vb0 = __float_as_uint(v0), vb1 = __float_as_uint(v1);
        unsigned vm  = __reduce_max_sync(0xFFFFFFFFu, vb0 > vb1 ? vb0 : vb1);
        unsigned m0  = __ballot_sync(0xFFFFFFFFu, vb0 == vm);
        unsigned m1  = __ballot_sync(0xFFFFFFFFu, vb1 == vm);
        bool win = m0 ? (lane == __ffs(m0) - 1) : (lane == __ffs(m1) - 1);
        if (win) {
            unsigned wp = m0 ? (unsigned)p0 : (unsigned)p1;
            s_red[o][wid] = ((unsigned long long)vm << 32)
                          | (0xFFFFFFFFu - wp);
        }
    }

    if (v0ok) {
        float ov = pv0;
        if (fabsf(pv0 - 0.5f) < 1e-3f) {
            float4 tb = s_t[po0];
            float ix = fmaxf(fminf(tb.z, ax2) - fmaxf(tb.x, ax1), 0.f);
            float iy = fmaxf(fminf(tb.w, ay2) - fmaxf(tb.y, ay1), 0.f);
            float in = ix * iy;
            ov = in / ((s_ta[po0] + aa) - in);   // exact near threshold
        }
        g_btov[b * NPRI + p0] = ov;
        g_bti [b * NPRI + p0] = (uint8_t)po0;
    }
    if (v1ok) {
        float ov = pv1;
        if (fabsf(pv1 - 0.5f) < 1e-3f) {
            float4 tb = s_t[po1];
            float ix = fmaxf(fminf(tb.z, bx2) - fmaxf(tb.x, bx1), 0.f);
            float iy = fmaxf(fminf(tb.w, by2) - fmaxf(tb.y, by1), 0.f);
            float in = ix * iy;
            ov = in / ((s_ta[po1] + ba) - in);
        }
        g_btov[b * NPRI + p1] = ov;
        g_bti [b * NPRI + p1] = (uint8_t)po1;
    }

    __syncthreads();
    if (tid < NOBJ) {
        unsigned long long m = 0ULL;
        #pragma unroll
        for (int w = 0; w < 8; w++) {
            unsigned long long u = s_red[tid][w];
            m = (u > m) ? u : m;
        }
        atomicMax(&g_best[b * NOBJ + tid], m);
    }
}

// ---------------- K2: force-assign + conf target + cross entropy (split) ------
// 4480 blocks x 256 threads: high occupancy hides the conf stream latency.
__global__ __launch_bounds__(256)
void k2_ce(const float* __restrict__ conf, const int* __restrict__ labels) {
    const int blk = blockIdx.x;
    const int b   = blk / CEB;
    const int t   = blk % CEB;
    const int tid = threadIdx.x;
    const int r0  = t * 256;
    const int nr  = min(256, NPRI - r0);

    __shared__ float    s_rows[256 * NCLS];
    __shared__ int      s_lab[NOBJ];
    __shared__ unsigned s_fp[NOBJ];
    __shared__ int      s_wc[8];

    if (tid < NOBJ) {
        s_lab[tid] = labels[b * NOBJ + tid];
        s_fp[tid]  = 0xFFFFFFFFu - (unsigned)(g_best[b * NOBJ + tid] & 0xFFFFFFFFULL);
    }
    const int nf4 = nr * NCLS / 4;
    const float4* src = (const float4*)(conf + ((size_t)b * NPRI + r0) * NCLS);
    #pragma unroll
    for (int i = 0; i < 6; i++) {
        int j = tid + i * 256;
        if (j < nf4) ((float4*)s_rows)[j] = src[j];
    }
    __syncthreads();

    int isp = 0;
    if (tid < nr) {
        int p = r0 + tid;
        size_t idx = (size_t)b * NPRI + p;
        float ov = g_btov[idx];
        int   o  = g_bti[idx];
        #pragma unroll
        for (int oo = 0; oo < NOBJ; oo++) {          // ascending: last truth wins
            bool f = (s_fp[oo] == (unsigned)p);
            ov = f ? 2.0f : ov;
            o  = f ? oo : o;
        }
        int ct = (ov < THRESH) ? 0 : (s_lab[o] + 1);
        g_ct[idx] = (uint8_t)ct;
        g_of[idx] = (uint8_t)o;
        isp = (ct > 0);
        const float* v = s_rows + tid * NCLS;        // stride 21: conflict-free
        float m = v[0];
        #pragma unroll
        for (int c = 1; c < NCLS; c++) m = fmaxf(m, v[c]);
        float ssum = 0.f;
        #pragma unroll
        for (int c = 0; c < NCLS; c++) ssum += __expf(v[c] - m);
        g_ce[idx] = m + __logf(ssum) - v[ct];
    }
    int c = __reduce_add_sync(0xFFFFFFFFu, isp);
    if ((tid & 31) == 0) s_wc[tid >> 5] = c;
    __syncthreads();
    if (tid == 0) {
        int cc = 0;
        #pragma unroll
        for (int w = 0; w < 8; w++) cc += s_wc[w];
        atomicAdd(&g_npos[b], cc);
    }
}

// ---------------- K3: loc loss + 2-bit radix top-K (1 bar/round) + final ------
__global__ __launch_bounds__(1024)
void k3_select(const float* __restrict__ loc_preds,
               const float* __restrict__ boxes,
               const float* __restrict__ priors,
               float* __restrict__ out) {
    const int b    = blockIdx.x;
    const int tid  = threadIdx.x;
    const int lane = tid & 31, wid = tid >> 5;

    __shared__ float s_tx1[NOBJ], s_ty1[NOBJ], s_tx2[NOBJ], s_ty2[NOBJ];
    __shared__ float s_redf[64];
    __shared__ int   s_cnt[2][3][32];
    __shared__ int   s_bc[4];

    if (tid < NOBJ) {
        s_tx1[tid] = boxes[(b * NOBJ + tid) * 4 + 0];
        s_ty1[tid] = boxes[(b * NOBJ + tid) * 4 + 1];
        s_tx2[tid] = boxes[(b * NOBJ + tid) * 4 + 2];
        s_ty2[tid] = boxes[(b * NOBJ + tid) * 4 + 3];
    }
    const int npos = g_npos[b];          // uniform load
    __syncthreads();

    unsigned u[9];
    float posce = 0.f, locsum = 0.f;
    #pragma unroll
    for (int i = 0; i < 9; i++) {
        int p = tid + i * 1024;
        u[i] = 0u;
        if (p < NPRI) {
            size_t idx = (size_t)b * NPRI + p;
            float ce = g_ce[idx];
            if (g_ct[idx] > 0) {
                posce += ce;
                int o = g_of[idx];
                float4 pr = ((const float4*)priors)[p];
                float tx1 = s_tx1[o], ty1 = s_ty1[o], tx2 = s_tx2[o], ty2 = s_ty2[o];
                float g0 = ((tx1 + tx2) * 0.5f - pr.x) / (0.1f * pr.z);
                float g1 = ((ty1 + ty2) * 0.5f - pr.y) / (0.1f * pr.w);
                float g2 = __logf((tx2 - tx1) / pr.z) * 5.0f;
                float g3 = __logf((ty2 - ty1) / pr.w) * 5.0f;
                float4 lp = ((const float4*)loc_preds)[(size_t)b * NPRI + p];
                locsum += sl1(lp.x - g0) + sl1(lp.y - g1)
                        + sl1(lp.z - g2) + sl1(lp.w - g3);
            } else {
                u[i] = __float_as_uint(ce);   // negatives only; ce >= 0
            }
        }
    }

    float2 pl = brSum2F(posce, locsum, s_redf);
    const float pcT = pl.x, lcT = pl.y;

    int K = 3 * npos; if (K > NPRI) K = NPRI;
    float negsum = 0.f;
    if (K > 0) {
        unsigned prefix = 0u;
        int par = 0;
        for (int sh = 29; sh >= 1; sh -= 2) {     // 2 bits/round, 1 barrier
            unsigned cA = prefix | (1u << sh);
            unsigned cB = prefix | (2u << sh);
            unsigned cC = prefix | (3u << sh);
            int n1 = 0, n2 = 0, n3 = 0;
            #pragma unroll
            for (int i = 0; i < 9; i++) {
                n1 += (u[i] >= cA);
                n2 += (u[i] >= cB);
                n3 += (u[i] >= cC);
            }
            n1 = __reduce_add_sync(0xFFFFFFFFu, n1);
            n2 = __reduce_add_sync(0xFFFFFFFFu, n2);
            n3 = __reduce_add_sync(0xFFFFFFFFu, n3);
            if (lane == 0) {
                s_cnt[par][0][wid] = n1;
                s_cnt[par][1][wid] = n2;
                s_cnt[par][2][wid] = n3;
            }
            __syncthreads();
            int t1 = __reduce_add_sync(0xFFFFFFFFu, s_cnt[par][0][lane]);
            int t2 = __reduce_add_sync(0xFFFFFFFFu, s_cnt[par][1][lane]);
            int t3 = __reduce_add_sync(0xFFFFFFFFu, s_cnt[par][2][lane]);
            prefix |= (t3 >= K) ? (3u << sh)
                    : (t2 >= K) ? (2u << sh)
                    : (t1 >= K) ? (1u << sh) : 0u;
            par ^= 1;
        }
        {   // final bit 0
            unsigned cand = prefix | 1u;
            int n = 0;
            #pragma unroll
            for (int i = 0; i < 9; i++) n += (u[i] >= cand);
            n = __reduce_add_sync(0xFFFFFFFFu, n);
            if (lane == 0) s_cnt[par][0][wid] = n;
            __syncthreads();
            int tot = __reduce_add_sync(0xFFFFFFFFu, s_cnt[par][0][lane]);
            if (tot >= K) prefix |= 1u;
        }
        float vK = __uint_as_float(prefix);       // exact K-th largest
        float sgt = 0.f; int cgt = 0;
        #pragma unroll
        for (int i = 0; i < 9; i++) {
            float v = __uint_as_float(u[i]);
            if (v > vK) { sgt += v; cgt++; }
        }
        float2 sc = brSum2F(sgt, (float)cgt, s_redf);   // cgt < 2^24: exact
        negsum = sc.x + ((float)K - sc.y) * vK;         // ties handled exactly
    }

    if (tid == 0) {
        g_locs[b]  = lcT;
        g_pces[b]  = pcT;
        g_negs[b]  = negsum;
        g_nposf[b] = (float)npos;
    }
    if (tid < NOBJ) g_best[b * NOBJ + tid] = 0ULL;   // re-zero for graph replay
    if (tid == 32)  g_npos[b] = 0;

    __threadfence();
    __syncthreads();
    if (tid == 0) {
        unsigned old = atomicAdd(&g_ticket, 1u);
        s_bc[2] = (old == BATCH - 1) ? 1 : 0;
    }
    __syncthreads();

    if (s_bc[2]) {   // last block: final reduction over images
        float np = 0.f, lc = 0.f, pc = 0.f, ns = 0.f;
        if (tid < BATCH) {
            np = __ldcg(&g_nposf[tid]);
            lc = __ldcg(&g_locs[tid]);
            pc = __ldcg(&g_pces[tid]);
            ns = __ldcg(&g_negs[tid]);
        }
        float2 r1 = brSum2F(np, lc, s_redf);
        float2 r2 = brSum2F(pc, ns, s_redf);
        if (tid == 0) {
            out[0] = (r2.x + r2.y) / (r1.x + 1e-7f) + r1.y / (4.0f * r1.x);
            g_ticket = 0u;
        }
    }
}

// ---------------- launch ------------------------------------------------------
extern "C" void kernel_launch(void* const* d_in, const int* in_sizes, int n_in,
                              void* d_out, int out_size) {
    const float* loc_preds  = (const float*)d_in[0];
    const float* conf_preds = (const float*)d_in[1];
    const float* boxes      = (const float*)d_in[2];
    const int*   labels     = (const int*)d_in[3];
    const float* priors     = (const float*)d_in[4];
    float* out = (float*)d_out;

    k1_match<<<BATCH * K1B, 256>>>(boxes, priors);
    k2_ce<<<BATCH * CEB, 256>>>(conf_preds, labels);
    k3_select<<<BATCH, 1024>>>(loc_preds, boxes, priors, out);
    (void)in_sizes; (void)n_in; (void)out_size;
}

// round 15
// speedup vs baseline: 1.2080x; 1.1143x over previous
#include <cuda_runtime.h>
#include <cstdint>

#define BATCH 128
#define NPRI  8732
#define NOBJ  16
#define NCLS  21
#define THRESH 0.5f
#define K1B   9         // k1 blocks per image (1024 priors each; 9*1024 >= 8732)
#define CEB   35        // k2 blocks per image (256 priors each)

// ---------------- scratch (static device globals; zero-initialized) ----------
__device__ float              g_btov[BATCH * NPRI];
__device__ uint8_t            g_bti [BATCH * NPRI];
__device__ float              g_ce  [BATCH * NPRI];   // neg_loss (0 for positives)
__device__ unsigned long long g_best[BATCH * NOBJ];   // re-zeroed by k3 each launch
__device__ float              g_pcep[BATCH * CEB];    // per-block posce partials
__device__ float              g_locp[BATCH * CEB];    // per-block loc partials
__device__ float              g_npp [BATCH * CEB];    // per-block npos partials
__device__ float              g_nposf[BATCH];
__device__ float              g_locs[BATCH];
__device__ float              g_pces[BATCH];
__device__ float              g_negs[BATCH];
__device__ unsigned int       g_ticket;               // reset by last block each launch

// ---------------- helpers -----------------------------------------------------
__device__ __forceinline__ float sl1(float x) {
    float a = fabsf(x);
    return (a < 1.f) ? 0.5f * a * a : a - 0.5f;
}

// two block-sums for one barrier set; s must hold 64 floats
__device__ __forceinline__ float2 brSum2F(float a, float b, float* s) {
    int lane = threadIdx.x & 31, wid = threadIdx.x >> 5;
    int nw = (blockDim.x + 31) >> 5;
    #pragma unroll
    for (int o = 16; o; o >>= 1) {
        a += __shfl_xor_sync(0xFFFFFFFFu, a, o);
        b += __shfl_xor_sync(0xFFFFFFFFu, b, o);
    }
    if (lane == 0) { s[wid] = a; s[32 + wid] = b; }
    __syncthreads();
    if (wid == 0) {
        float ra = (lane < nw) ? s[lane] : 0.f;
        float rb = (lane < nw) ? s[32 + lane] : 0.f;
        #pragma unroll
        for (int o = 16; o; o >>= 1) {
            ra += __shfl_xor_sync(0xFFFFFFFFu, ra, o);
            rb += __shfl_xor_sync(0xFFFFFFFFu, rb, o);
        }
        if (lane == 0) { s[0] = ra; s[32] = rb; }
    }
    __syncthreads();
    float2 r = make_float2(s[0], s[32]);
    __syncthreads();
    return r;
}

// ---------------- K1: matching, 4 priors per thread ---------------------------
__global__ __launch_bounds__(256)
void k1_match(const float* __restrict__ boxes, const float* __restrict__ priors) {
    const int b    = blockIdx.x / K1B;
    const int t    = blockIdx.x % K1B;
    const int tid  = threadIdx.x;
    const int lane = tid & 31, wid = tid >> 5;
    const int base = t * 1024;

    __shared__ float4 s_t[NOBJ];
    __shared__ float  s_ta[NOBJ];
    __shared__ unsigned long long s_red[NOBJ][8];

    if (tid < NOBJ) {
        float4 tb = ((const float4*)boxes)[b * NOBJ + tid];
        s_t[tid]  = tb;
        s_ta[tid] = (tb.z - tb.x) * (tb.w - tb.y);
    }
    __syncthreads();

    int   P[4];  bool ok[4];
    float x1[4], y1[4], x2[4], y2[4], ar[4];
    #pragma unroll
    for (int q = 0; q < 4; q++) {
        P[q]  = base + q * 256 + tid;
        ok[q] = (P[q] < NPRI);
        // invalid -> far degenerate box: IoU = 0, larger p loses ties anyway
        x1[q] = 2.f; y1[q] = 2.f; x2[q] = 2.f; y2[q] = 2.f; ar[q] = 0.f;
        if (ok[q]) {
            float4 pr = ((const float4*)priors)[P[q]];
            float hw = 0.5f * pr.z, hh = 0.5f * pr.w;
            x1[q] = pr.x - hw; y1[q] = pr.y - hh;
            x2[q] = pr.x + hw; y2[q] = pr.y + hh;
            ar[q] = pr.z * pr.w;
        }
    }

    float pv[4] = {-1.f, -1.f, -1.f, -1.f};
    int   po[4] = {0, 0, 0, 0};
    #pragma unroll
    for (int o = 0; o < NOBJ; o++) {
        float4 tb = s_t[o]; float ta = s_ta[o];
        unsigned vb[4];
        #pragma unroll
        for (int q = 0; q < 4; q++) {
            float ix = fmaxf(fminf(tb.z, x2[q]) - fmaxf(tb.x, x1[q]), 0.f);
            float iy = fmaxf(fminf(tb.w, y2[q]) - fmaxf(tb.y, y1[q]), 0.f);
            float in = ix * iy;
            float v  = __fdividef(in, (ta + ar[q]) - in);   // ordering only
            bool g = v > pv[q];                             // first truth on tie
            pv[q] = g ? v : pv[q];  po[q] = g ? o : po[q];
            vb[q] = __float_as_uint(v);
        }
        // per-truth warp max; ties -> smallest p (group order q0<q1<q2<q3)
        unsigned vmx = vb[0] > vb[1] ? vb[0] : vb[1];
        unsigned vmy = vb[2] > vb[3] ? vb[2] : vb[3];
        unsigned vm  = __reduce_max_sync(0xFFFFFFFFu, vmx > vmy ? vmx : vmy);
        unsigned m0 = __ballot_sync(0xFFFFFFFFu, vb[0] == vm);
        unsigned m1 = __ballot_sync(0xFFFFFFFFu, vb[1] == vm);
        unsigned m2 = __ballot_sync(0xFFFFFFFFu, vb[2] == vm);
        unsigned m3 = __ballot_sync(0xFFFFFFFFu, vb[3] == vm);
        int wq = m0 ? 0 : (m1 ? 1 : (m2 ? 2 : 3));
        unsigned mq = m0 ? m0 : (m1 ? m1 : (m2 ? m2 : m3));
        if (lane == __ffs(mq) - 1)
            s_red[o][wid] = ((unsigned long long)vm << 32)
                          | (0xFFFFFFFFu - (unsigned)P[wq]);
    }

    // per-prior store; exact div.rn only near the 0.5 threshold
    #pragma unroll
    for (int q = 0; q < 4; q++) {
        if (!ok[q]) continue;
        float ov = pv[q];
        if (fabsf(ov - 0.5f) < 1e-3f) {
            float4 tb = s_t[po[q]];
            float ix = fmaxf(fminf(tb.z, x2[q]) - fmaxf(tb.x, x1[q]), 0.f);
            float iy = fmaxf(fminf(tb.w, y2[q]) - fmaxf(tb.y, y1[q]), 0.f);
            float in = ix * iy;
            ov = in / ((s_ta[po[q]] + ar[q]) - in);
        }
        g_btov[b * NPRI + P[q]] = ov;
        g_bti [b * NPRI + P[q]] = (uint8_t)po[q];
    }

    __syncthreads();
    if (tid < NOBJ) {
        unsigned long long m = 0ULL;
        #pragma unroll
        for (int w = 0; w < 8; w++) {
            unsigned long long u = s_red[tid][w];
            m = (u > m) ? u : m;
        }
        atomicMax(&g_best[b * NOBJ + tid], m);
    }
}

// ---------------- K2: ce + targets + loc loss, per-block partials --------------
__global__ __launch_bounds__(256)
void k2_ce(const float* __restrict__ conf, const int* __restrict__ labels,
           const float* __restrict__ loc_preds, const float* __restrict__ boxes,
           const float* __restrict__ priors) {
    const int blk = blockIdx.x;
    const int b   = blk / CEB;
    const int t   = blk % CEB;
    const int tid = threadIdx.x;
    const int r0  = t * 256;
    const int nr  = min(256, NPRI - r0);

    __shared__ float    s_rows[256 * NCLS];
    __shared__ float4   s_t[NOBJ];
    __shared__ int      s_lab[NOBJ];
    __shared__ unsigned s_fp[NOBJ];
    __shared__ float    s_redf[64];

    if (tid < NOBJ) {
        s_t[tid]   = ((const float4*)boxes)[b * NOBJ + tid];
        s_lab[tid] = labels[b * NOBJ + tid];
        s_fp[tid]  = 0xFFFFFFFFu - (unsigned)(g_best[b * NOBJ + tid] & 0xFFFFFFFFULL);
    }
    const int nf4 = nr * NCLS / 4;
    const float4* src = (const float4*)(conf + ((size_t)b * NPRI + r0) * NCLS);
    #pragma unroll
    for (int i = 0; i < 6; i++) {
        int j = tid + i * 256;
        if (j < nf4) ((float4*)s_rows)[j] = src[j];
    }
    __syncthreads();

    float posce = 0.f, locsum = 0.f;
    int isp = 0;
    if (tid < nr) {
        int p = r0 + tid;
        size_t idx = (size_t)b * NPRI + p;
        float ov = g_btov[idx];
        int   o  = g_bti[idx];
        #pragma unroll
        for (int oo = 0; oo < NOBJ; oo++) {          // ascending: last truth wins
            bool f = (s_fp[oo] == (unsigned)p);
            ov = f ? 2.0f : ov;
            o  = f ? oo : o;
        }
        int ct = (ov < THRESH) ? 0 : (s_lab[o] + 1);
        const float* v = s_rows + tid * NCLS;        // stride 21: conflict-free
        float m = v[0];
        #pragma unroll
        for (int c = 1; c < NCLS; c++) m = fmaxf(m, v[c]);
        float ssum = 0.f;
        #pragma unroll
        for (int c = 0; c < NCLS; c++) ssum += __expf(v[c] - m);
        float ce = m + __logf(ssum) - v[ct];
        if (ct > 0) {
            posce = ce; isp = 1;
            float4 tb = s_t[o];
            float4 pr = ((const float4*)priors)[p];
            float g0 = ((tb.x + tb.z) * 0.5f - pr.x) / (0.1f * pr.z);
            float g1 = ((tb.y + tb.w) * 0.5f - pr.y) / (0.1f * pr.w);
            float g2 = __logf((tb.z - tb.x) / pr.z) * 5.0f;
            float g3 = __logf((tb.w - tb.y) / pr.w) * 5.0f;
            float4 lp = ((const float4*)loc_preds)[idx];
            locsum = sl1(lp.x - g0) + sl1(lp.y - g1)
                   + sl1(lp.z - g2) + sl1(lp.w - g3);
            ce = 0.f;                                 // neg_loss = 0 for positives
        }
        g_ce[idx] = ce;
    }
    float2 pl = brSum2F(posce, locsum, s_redf);
    float2 nn = brSum2F((float)isp, 0.f, s_redf);
    if (tid == 0) {
        g_pcep[blk] = pl.x;
        g_locp[blk] = pl.y;
        g_npp [blk] = nn.x;
    }
}

// ---------------- K3: lean top-K select + partial merge + fused final ----------
__global__ __launch_bounds__(1024)
void k3_select(float* __restrict__ out) {
    const int b    = blockIdx.x;
    const int tid  = threadIdx.x;
    const int lane = tid & 31, wid = tid >> 5;

    __shared__ float s_redf[64];
    __shared__ int   s_cnt[2][3][32];
    __shared__ int   s_bc[4];

    // merge per-block partials (35 per image)
    float pp = 0.f, lp = 0.f, np = 0.f;
    if (tid < CEB) {
        pp = g_pcep[b * CEB + tid];
        lp = g_locp[b * CEB + tid];
        np = g_npp [b * CEB + tid];
    }
    float2 m1 = brSum2F(np, pp, s_redf);
    float2 m2 = brSum2F(lp, 0.f, s_redf);
    const int   npos = (int)m1.x;
    const float pcT  = m1.y, lcT = m2.x;

    unsigned u[9];
    #pragma unroll
    for (int i = 0; i < 9; i++) {
        int p = tid + i * 1024;
        u[i] = (p < NPRI) ? __float_as_uint(g_ce[(size_t)b * NPRI + p]) : 0u;
    }

    int K = 3 * npos; if (K > NPRI) K = NPRI;
    float negsum = 0.f;
    if (K > 0) {
        unsigned prefix = 0u;
        int par = 0;
        for (int sh = 29; sh >= 1; sh -= 2) {     // 2 bits/round, 1 barrier
            unsigned cA = prefix | (1u << sh);
            unsigned cB = prefix | (2u << sh);
            unsigned cC = prefix | (3u << sh);
            int n1 = 0, n2 = 0, n3 = 0;
            #pragma unroll
            for (int i = 0; i < 9; i++) {
                n1 += (u[i] >= cA);
                n2 += (u[i] >= cB);
                n3 += (u[i] >= cC);
            }
            n1 = __reduce_add_sync(0xFFFFFFFFu, n1);
            n2 = __reduce_add_sync(0xFFFFFFFFu, n2);
            n3 = __reduce_add_sync(0xFFFFFFFFu, n3);
            if (lane == 0) {
                s_cnt[par][0][wid] = n1;
                s_cnt[par][1][wid] = n2;
                s_cnt[par][2][wid] = n3;
            }
            __syncthreads();
            int t1 = __reduce_add_sync(0xFFFFFFFFu, s_cnt[par][0][lane]);
            int t2 = __reduce_add_sync(0xFFFFFFFFu, s_cnt[par][1][lane]);
            int t3 = __reduce_add_sync(0xFFFFFFFFu, s_cnt[par][2][lane]);
            prefix |= (t3 >= K) ? (3u << sh)
                    : (t2 >= K) ? (2u << sh)
                    : (t1 >= K) ? (1u << sh) : 0u;
            par ^= 1;
        }
        {   // final bit 0
            unsigned cand = prefix | 1u;
            int n = 0;
            #pragma unroll
            for (int i = 0; i < 9; i++) n += (u[i] >= cand);
            n = __reduce_add_sync(0xFFFFFFFFu, n);
            if (lane == 0) s_cnt[par][0][wid] = n;
            __syncthreads();
            int tot = __reduce_add_sync(0xFFFFFFFFu, s_cnt[par][0][lane]);
            if (tot >= K) prefix |= 1u;
        }
        float vK = __uint_as_float(prefix);       // exact K-th largest
        float sgt = 0.f; int cgt = 0;
        #pragma unroll
        for (int i = 0; i < 9; i++) {
            float v = __uint_as_float(u[i]);
            if (v > vK) { sgt += v; cgt++; }
        }
        float2 sc = brSum2F(sgt, (float)cgt, s_redf);   // cgt < 2^24: exact
        negsum = sc.x + ((float)K - sc.y) * vK;         // ties handled exactly
    }

    if (tid == 0) {
        g_locs[b]  = lcT;
        g_pces[b]  = pcT;
        g_negs[b]  = negsum;
        g_nposf[b] = (float)npos;
    }
    if (tid < NOBJ) g_best[b * NOBJ + tid] = 0ULL;   // re-zero for graph replay

    __threadfence();
    __syncthreads();
    if (tid == 0) {
        unsigned old = atomicAdd(&g_ticket, 1u);
        s_bc[2] = (old == BATCH - 1) ? 1 : 0;
    }
    __syncthreads();

    if (s_bc[2]) {   // last block: final reduction over images
        float np2 = 0.f, lc = 0.f, pc = 0.f, ns = 0.f;
        if (tid < BATCH) {
            np2 = __ldcg(&g_nposf[tid]);
            lc  = __ldcg(&g_locs[tid]);
            pc  = __ldcg(&g_pces[tid]);
            ns  = __ldcg(&g_negs[tid]);
        }
        float2 r1 = brSum2F(np2, lc, s_redf);
        float2 r2 = brSum2F(pc, ns, s_redf);
        if (tid == 0) {
            out[0] = (r2.x + r2.y) / (r1.x + 1e-7f) + r1.y / (4.0f * r1.x);
            g_ticket = 0u;
        }
    }
}

// ---------------- launch ------------------------------------------------------
extern "C" void kernel_launch(void* const* d_in, const int* in_sizes, int n_in,
                              void* d_out, int out_size) {
    const float* loc_preds  = (const float*)d_in[0];
    const float* conf_preds = (const float*)d_in[1];
    const float* boxes      = (const float*)d_in[2];
    const int*   labels     = (const int*)d_in[3];
    const float* priors     = (const float*)d_in[4];
    float* out = (float*)d_out;

    k1_match<<<BATCH * K1B, 256>>>(boxes, priors);
    k2_ce<<<BATCH * CEB, 256>>>(conf_preds, labels, loc_preds, boxes, priors);
    k3_select<<<BATCH, 1024>>>(out);
    (void)in_sizes; (void)n_in; (void)out_size;
}